// round 3
// baseline (speedup 1.0000x reference)
#include <cuda_runtime.h>
#include <cstdint>

#define KN    64
#define ZD    16
#define BLOCK 256
#define RPT   8                 // rows per thread (4 f32x2 pairs)
#define TILE  (BLOCK * RPT)     // 2048 rows per block

// ---------- f32x2 packed helpers (Blackwell sm_103a) ----------
__device__ __forceinline__ unsigned long long pack2(float a, float b) {
    unsigned long long r;
    asm("mov.b64 %0, {%1, %2};" : "=l"(r)
        : "r"(__float_as_uint(a)), "r"(__float_as_uint(b)));
    return r;
}
__device__ __forceinline__ void unpack2(unsigned long long p, float& a, float& b) {
    unsigned int x, y;
    asm("mov.b64 {%0, %1}, %2;" : "=r"(x), "=r"(y) : "l"(p));
    a = __uint_as_float(x);
    b = __uint_as_float(y);
}
__device__ __forceinline__ unsigned long long fma2(unsigned long long a,
                                                   unsigned long long b,
                                                   unsigned long long c) {
    unsigned long long d;
    asm("fma.rn.f32x2 %0, %1, %2, %3;" : "=l"(d) : "l"(a), "l"(b), "l"(c));
    return d;
}

// tanh(x) = 1 - 2/(e^{2x}+1), via MUFU EX2 + RCP. ~1e-6 rel err, saturates
// correctly at +/-inf (ex2(inf)=inf -> rcp=0 -> 1 ; ex2(-inf)=0 -> rcp(1)=1 -> -1).
__device__ __forceinline__ float tanh_fast(float x) {
    float t, r;
    // 2x * log2(e) = x * 2.885390081777927
    asm("ex2.approx.f32 %0, %1;" : "=f"(t) : "f"(x * 2.885390081777927f));
    asm("rcp.approx.f32 %0, %1;" : "=f"(r) : "f"(t + 1.0f));
    return fmaf(-2.0f, r, 1.0f);
}

__global__ void __launch_bounds__(BLOCK, 1) mave_main(
    const float* __restrict__ z, const float* __restrict__ a0p,
    const float* __restrict__ bk, const float* __restrict__ ck,
    const float* __restrict__ dk, float* __restrict__ out)
{
    __shared__ unsigned long long cs2[KN * ZD];  // ck duplicated (c,c) pairs, 8 KB
    __shared__ float bks[KN];
    __shared__ float dks[KN];

    const int tid = threadIdx.x;

    for (int i = tid; i < KN * ZD; i += BLOCK) {
        float c = ck[i];
        cs2[i] = pack2(c, c);
    }
    if (tid < KN) { bks[tid] = bk[tid]; dks[tid] = dk[tid]; }
    __syncthreads();

    const long base = (long)blockIdx.x * TILE;

    // Load 8 rows of z (rows base+tid+i*BLOCK), pack row-pairs into f32x2.
    unsigned long long zz[4][ZD];
    #pragma unroll
    for (int p = 0; p < 4; ++p) {
        const long r0 = base + tid + (long)(2 * p) * BLOCK;
        const long r1 = r0 + BLOCK;
        const float4* z0 = reinterpret_cast<const float4*>(z + r0 * ZD);
        const float4* z1 = reinterpret_cast<const float4*>(z + r1 * ZD);
        #pragma unroll
        for (int q = 0; q < 4; ++q) {
            float4 u = z0[q];
            float4 v = z1[q];
            zz[p][q * 4 + 0] = pack2(u.x, v.x);
            zz[p][q * 4 + 1] = pack2(u.y, v.y);
            zz[p][q * 4 + 2] = pack2(u.z, v.z);
            zz[p][q * 4 + 3] = pack2(u.w, v.w);
        }
    }

    const float a0 = a0p[0];
    float acc[RPT];
    #pragma unroll
    for (int i = 0; i < RPT; ++i) acc[i] = a0;

    #pragma unroll 4
    for (int k = 0; k < KN; ++k) {
        const float dv = dks[k];
        unsigned long long h0 = pack2(dv, dv);
        unsigned long long h1 = h0, h2 = h0, h3 = h0;
        const unsigned long long* cr = &cs2[k * ZD];
        #pragma unroll
        for (int zi = 0; zi < ZD; ++zi) {
            const unsigned long long c2 = cr[zi];  // LDS.64, warp-uniform broadcast
            h0 = fma2(zz[0][zi], c2, h0);
            h1 = fma2(zz[1][zi], c2, h1);
            h2 = fma2(zz[2][zi], c2, h2);
            h3 = fma2(zz[3][zi], c2, h3);
        }
        const float bv = bks[k];
        float x0, x1;
        unpack2(h0, x0, x1);
        acc[0] = fmaf(bv, tanh_fast(x0), acc[0]);
        acc[1] = fmaf(bv, tanh_fast(x1), acc[1]);
        unpack2(h1, x0, x1);
        acc[2] = fmaf(bv, tanh_fast(x0), acc[2]);
        acc[3] = fmaf(bv, tanh_fast(x1), acc[3]);
        unpack2(h2, x0, x1);
        acc[4] = fmaf(bv, tanh_fast(x0), acc[4]);
        acc[5] = fmaf(bv, tanh_fast(x1), acc[5]);
        unpack2(h3, x0, x1);
        acc[6] = fmaf(bv, tanh_fast(x0), acc[6]);
        acc[7] = fmaf(bv, tanh_fast(x1), acc[7]);
    }

    #pragma unroll
    for (int i = 0; i < RPT; ++i) {
        out[base + tid + (long)i * BLOCK] = acc[i];
    }
}

// Generic scalar tail (only used if B % TILE != 0; B=2M divides evenly).
__global__ void mave_tail(
    const float* __restrict__ z, const float* __restrict__ a0p,
    const float* __restrict__ bk, const float* __restrict__ ck,
    const float* __restrict__ dk, float* __restrict__ out,
    long start, long Btot)
{
    long row = start + (long)blockIdx.x * blockDim.x + threadIdx.x;
    if (row >= Btot) return;
    const float* zr = z + row * ZD;
    float zv[ZD];
    #pragma unroll
    for (int i = 0; i < ZD; ++i) zv[i] = zr[i];
    float acc = a0p[0];
    for (int k = 0; k < KN; ++k) {
        float h = dk[k];
        #pragma unroll
        for (int zi = 0; zi < ZD; ++zi) h = fmaf(ck[k * ZD + zi], zv[zi], h);
        acc = fmaf(bk[k], tanh_fast(h), acc);
    }
    out[row] = acc;
}

extern "C" void kernel_launch(void* const* d_in, const int* in_sizes, int n_in,
                              void* d_out, int out_size) {
    const float* z  = (const float*)d_in[0];
    const float* a0 = (const float*)d_in[1];
    const float* bk = (const float*)d_in[2];
    const float* ck = (const float*)d_in[3];
    const float* dk = (const float*)d_in[4];
    float* out = (float*)d_out;

    const long B = (long)in_sizes[0] / ZD;
    const long nfull = B / TILE;

    if (nfull > 0) {
        mave_main<<<(int)nfull, BLOCK>>>(z, a0, bk, ck, dk, out);
    }
    const long rem = B - nfull * TILE;
    if (rem > 0) {
        mave_tail<<<(int)((rem + 255) / 256), 256>>>(z, a0, bk, ck, dk, out,
                                                     nfull * TILE, B);
    }
}

// round 5
// speedup vs baseline: 2.7169x; 2.7169x over previous
#include <cuda_runtime.h>
#include <cuda_bf16.h>
#include <cstdint>

#define ZD            16
#define KN            64
#define NTHREADS      256
#define WARPS         8
#define TPW           16                       // 16-row blocks per warp
#define ROWS_PER_WARP (TPW * 16)               // 256
#define ROWS_PER_CTA  (WARPS * ROWS_PER_WARP)  // 2048

// ---- helpers ---------------------------------------------------------------
// pack two floats to bf16x2: lower half = lo, upper half = hi
__device__ __forceinline__ uint32_t pack_bf2(float lo, float hi) {
    uint32_t r;
    asm("cvt.rn.bf16x2.f32 %0, %1, %2;" : "=r"(r) : "f"(hi), "f"(lo));
    return r;
}
// split float2 {x,y} into bf16x2 hi part and bf16x2 residual (lo) part
__device__ __forceinline__ void split_bf2(float x, float y, uint32_t& hi, uint32_t& lo) {
    uint32_t h = pack_bf2(x, y);
    float xh = __uint_as_float(h << 16);
    float yh = __uint_as_float(h & 0xFFFF0000u);
    hi = h;
    lo = pack_bf2(x - xh, y - yh);
}
__device__ __forceinline__ float tanh_a(float x) {
    float r;
    asm("tanh.approx.f32 %0, %1;" : "=f"(r) : "f"(x));
    return r;
}
// D = A(16x16 bf16, row) x B(16x8 bf16, col) + C, fp32 accum
__device__ __forceinline__ void mma16816(float* d,
                                         const uint32_t* a,
                                         uint32_t b0, uint32_t b1,
                                         const float* c) {
    asm("mma.sync.aligned.m16n8k16.row.col.f32.bf16.bf16.f32 "
        "{%0,%1,%2,%3}, {%4,%5,%6,%7}, {%8,%9}, {%10,%11,%12,%13};"
        : "=f"(d[0]), "=f"(d[1]), "=f"(d[2]), "=f"(d[3])
        : "r"(a[0]), "r"(a[1]), "r"(a[2]), "r"(a[3]),
          "r"(b0), "r"(b1),
          "f"(c[0]), "f"(c[1]), "f"(c[2]), "f"(c[3]));
}

// ---- main kernel -----------------------------------------------------------
__global__ void __launch_bounds__(NTHREADS) mave_mma(
    const float* __restrict__ z, const float* __restrict__ a0p,
    const float* __restrict__ bkp, const float* __restrict__ ck,
    const float* __restrict__ dkp, float* __restrict__ out)
{
    __shared__ float2 sdkbk[KN];   // {dk, bk} per hidden node

    const int tid  = threadIdx.x;
    const int wid  = tid >> 5;
    const int lane = tid & 31;
    const int quad = lane >> 2;     // 0..7  (row group / B-column within tile)
    const int qid  = lane & 3;      // 0..3  (k-pair / column pair)

    if (tid < KN) {
        float2 v; v.x = dkp[tid]; v.y = bkp[tid];
        sdkbk[tid] = v;
    }
    __syncthreads();
    const float a0 = a0p[0];

    // ---- preload constant B fragments (ck hi/lo), 8 n-tiles ----
    // B(k, n) = ck[n, k]; thread's column n = j*8 + quad, k = qid*2 (+8 for b1)
    uint32_t bhi[8][2], blo[8][2];
    #pragma unroll
    for (int j = 0; j < 8; ++j) {
        const float* cr = ck + (j * 8 + quad) * ZD + qid * 2;
        float2 g0 = *reinterpret_cast<const float2*>(cr);
        float2 g1 = *reinterpret_cast<const float2*>(cr + 8);
        split_bf2(g0.x, g0.y, bhi[j][0], blo[j][0]);
        split_bf2(g1.x, g1.y, bhi[j][1], blo[j][1]);
    }
    // per-thread dk/bk for its two columns in each tile (col = j*8 + qid*2 + {0,1})
    float2 db[8][2];
    #pragma unroll
    for (int j = 0; j < 8; ++j) {
        db[j][0] = sdkbk[j * 8 + qid * 2];
        db[j][1] = sdkbk[j * 8 + qid * 2 + 1];
    }

    const long warp_base = (long)blockIdx.x * ROWS_PER_CTA + (long)wid * ROWS_PER_WARP;

    // A-fragment loads: row r0 = base + quad, r1 = r0 + 8, k offsets qid*2 and qid*2+8
    const float* zp = z + (warp_base + quad) * ZD + qid * 2;

    // prefetch block 0
    float2 p0 = *reinterpret_cast<const float2*>(zp);
    float2 p1 = *reinterpret_cast<const float2*>(zp + 8 * ZD);
    float2 p2 = *reinterpret_cast<const float2*>(zp + 8);
    float2 p3 = *reinterpret_cast<const float2*>(zp + 8 * ZD + 8);

    #pragma unroll 1
    for (int blk = 0; blk < TPW; ++blk) {
        // split current z into A hi/lo fragments
        uint32_t ahi[4], alo[4];
        split_bf2(p0.x, p0.y, ahi[0], alo[0]);
        split_bf2(p1.x, p1.y, ahi[1], alo[1]);
        split_bf2(p2.x, p2.y, ahi[2], alo[2]);
        split_bf2(p3.x, p3.y, ahi[3], alo[3]);

        // prefetch next block while MMAs run
        if (blk + 1 < TPW) {
            const float* znx = zp + (long)(blk + 1) * 16 * ZD;
            p0 = *reinterpret_cast<const float2*>(znx);
            p1 = *reinterpret_cast<const float2*>(znx + 8 * ZD);
            p2 = *reinterpret_cast<const float2*>(znx + 8);
            p3 = *reinterpret_cast<const float2*>(znx + 8 * ZD + 8);
        }

        float racc0 = 0.f, racc1 = 0.f;
        const float zero4[4] = {0.f, 0.f, 0.f, 0.f};

        #pragma unroll
        for (int j = 0; j < 8; ++j) {
            float d[4];
            mma16816(d, ahi, bhi[j][0], bhi[j][1], zero4);  // hi*hi
            mma16816(d, ahi, blo[j][0], blo[j][1], d);      // hi*lo
            mma16816(d, alo, bhi[j][0], bhi[j][1], d);      // lo*hi

            const float2 db0 = db[j][0];
            const float2 db1 = db[j][1];
            racc0 = fmaf(tanh_a(d[0] + db0.x), db0.y, racc0);
            racc0 = fmaf(tanh_a(d[1] + db1.x), db1.y, racc0);
            racc1 = fmaf(tanh_a(d[2] + db0.x), db0.y, racc1);
            racc1 = fmaf(tanh_a(d[3] + db1.x), db1.y, racc1);
        }

        // reduce across the 4 lanes of the quad (they hold disjoint columns)
        racc0 += __shfl_xor_sync(0xFFFFFFFFu, racc0, 1);
        racc0 += __shfl_xor_sync(0xFFFFFFFFu, racc0, 2);
        racc1 += __shfl_xor_sync(0xFFFFFFFFu, racc1, 1);
        racc1 += __shfl_xor_sync(0xFFFFFFFFu, racc1, 2);

        if (qid == 0) {
            const long r0 = warp_base + (long)blk * 16 + quad;
            out[r0]     = a0 + racc0;
            out[r0 + 8] = a0 + racc1;
        }
    }
}

// ---- scalar tail (unused when B % 2048 == 0; B = 2M is) --------------------
__global__ void mave_tail(
    const float* __restrict__ z, const float* __restrict__ a0p,
    const float* __restrict__ bk, const float* __restrict__ ck,
    const float* __restrict__ dk, float* __restrict__ out,
    long start, long Btot)
{
    long row = start + (long)blockIdx.x * blockDim.x + threadIdx.x;
    if (row >= Btot) return;
    const float* zr = z + row * ZD;
    float zv[ZD];
    #pragma unroll
    for (int i = 0; i < ZD; ++i) zv[i] = zr[i];
    float acc = a0p[0];
    for (int k = 0; k < KN; ++k) {
        float h = dk[k];
        #pragma unroll
        for (int zi = 0; zi < ZD; ++zi) h = fmaf(ck[k * ZD + zi], zv[zi], h);
        acc = fmaf(bk[k], tanh_a(h), acc);
    }
    out[row] = acc;
}

extern "C" void kernel_launch(void* const* d_in, const int* in_sizes, int n_in,
                              void* d_out, int out_size) {
    const float* z  = (const float*)d_in[0];
    const float* a0 = (const float*)d_in[1];
    const float* bk = (const float*)d_in[2];
    const float* ck = (const float*)d_in[3];
    const float* dk = (const float*)d_in[4];
    float* out = (float*)d_out;

    const long B = (long)in_sizes[0] / ZD;
    const long nfull = B / ROWS_PER_CTA;

    if (nfull > 0) {
        mave_mma<<<(int)nfull, NTHREADS>>>(z, a0, bk, ck, dk, out);
    }
    const long rem = B - nfull * ROWS_PER_CTA;
    if (rem > 0) {
        mave_tail<<<(int)((rem + 255) / 256), 256>>>(z, a0, bk, ck, dk, out,
                                                     nfull * ROWS_PER_CTA, B);
    }
}